// round 14
// baseline (speedup 1.0000x reference)
#include <cuda_runtime.h>

// ISTSimulator: B=65536, V=2, L=200 per-lane recurrence.
// Round 14: 2 lanes per thread, scalar interleaved (double per-warp ILP).
// BT=64, block covers 128 lanes (thread t owns lanes t and t+64) -> grid 1024
// (keeps R13's 1% SM quantization). Math per lane identical to R13:
// Taylor-propagated D + geometric sigmoid F, 16-step exact MUFU reseeds,
// warp-uniform hazard votes, FFMA.SAT clamp. 32-step smem staging, stride-33.

#define LOG2E_F 1.4426950408889634f
#define SW 33                          // smem row stride (odd -> conflict-free)
#define BT 64                          // threads per block
#define ROWS 128                       // lanes per block

__device__ __forceinline__ float ex2a(float x) {
    float r; asm("ex2.approx.ftz.f32 %0, %1;" : "=f"(r) : "f"(x)); return r;
}
__device__ __forceinline__ float lg2a(float x) {
    float r; asm("lg2.approx.f32 %0, %1;" : "=f"(r) : "f"(x)); return r;
}
__device__ __forceinline__ float rcpa(float x) {
    float r; asm("rcp.approx.ftz.f32 %0, %1;" : "=f"(r) : "f"(x)); return r;
}

struct LS {                            // per-lane state + params
    float u, F;
    float lam, nlam, beta, nbeta, c2;
    float kd, nkd, kf, mu;
    float na, z0, c;
};

__device__ __forceinline__ void ls_init(LS& s, const float* p) {
    s.lam  = 0.001f * fmaxf(p[0], 0.0f);
    s.nlam = -s.lam;
    s.beta = fmaf(10.0f, fmaxf(p[1], 0.0f), 1.0f);
    s.nbeta = -s.beta;
    s.c2   = 0.5f * s.beta * (s.beta - 1.0f);
    s.kd   = p[2];
    s.nkd  = -s.kd;
    s.mu   = p[3];
    s.kf   = p[4];
    float a = LOG2E_F / p[6];
    s.z0 = p[5] * a;
    s.na = -a;
    s.c  = ex2a(s.na);
    s.u  = 1.0f;                       // u = 1 - D; stays in (0.38, 1]
    s.F  = 1e-12f;
}

// Fast path: Taylor-propagated D + geometric sigmoid, exact reseed at entry.
template <int LEN>
__device__ __forceinline__ void group_fast(LS& s0, LS& s1,
                                           float* sp0, float* sp1, int n0g)
{
    float zs0 = fmaf((float)n0g, s0.na, s0.z0);
    float zs1 = fmaf((float)n0g, s1.na, s1.z0);
    float l0  = lg2a(s0.u),            l1  = lg2a(s1.u);
    float pw0 = ex2a(s0.beta * l0),    pw1 = ex2a(s1.beta * l1);
    float d0  = s0.lam * pw0,          d1  = s1.lam * pw1;
    float r0  = rcpa(s0.u),            r1  = rcpa(s1.u);
    float e0  = ex2a(zs0),             e1  = ex2a(zs1);
    #pragma unroll
    for (int jj = 0; jj < LEN; ++jj) {
        float g0 = rcpa(1.0f + e0);    float g1 = rcpa(1.0f + e1);
        e0 *= s0.c;                    e1 *= s1.c;
        float q0 = fmaf(s0.mu, s0.F, 1e-12f);
        float q1 = fmaf(s1.mu, s1.F, 1e-12f);
        s0.F = __saturatef(fmaf(g0, q0, s0.F));
        s1.F = __saturatef(fmaf(g1, q1, s1.F));
        float x0 = d0 * r0;            float x1 = d1 * r1;
        s0.u -= d0;                    s1.u -= d1;
        float t0 = fmaf(s0.c2, x0, s0.nbeta);
        float t1 = fmaf(s1.c2, x1, s1.nbeta);
        d0 *= fmaf(t0, x0, 1.0f);      d1 *= fmaf(t1, x1, 1.0f);
        float a0 = fmaf(s0.u, r0, -2.0f);
        float a1 = fmaf(s1.u, r1, -2.0f);
        r0 = -r0 * a0;                 r1 = -r1 * a1;   // Newton 1/u
        sp0[jj] = fmaf(s0.kf, s0.F, fmaf(s0.nkd, s0.u, s0.kd));
        sp1[jj] = fmaf(s1.kf, s1.F, fmaf(s1.nkd, s1.u, s1.kd));
    }
}

// Exact path: per-step lg2/ex2 pow + per-step saturating ex2 sigmoid (R8 math).
template <int LEN>
__device__ __forceinline__ void group_exact(LS& s0, LS& s1,
                                            float* sp0, float* sp1, int n0g)
{
    float zs0 = fmaf((float)n0g, s0.na, s0.z0);
    float zs1 = fmaf((float)n0g, s1.na, s1.z0);
    #pragma unroll
    for (int jj = 0; jj < LEN; ++jj) {
        float l0  = lg2a(s0.u),         l1  = lg2a(s1.u);
        float pw0 = ex2a(s0.beta * l0), pw1 = ex2a(s1.beta * l1);
        s0.u = fmaf(s0.nlam, pw0, s0.u);
        s1.u = fmaf(s1.nlam, pw1, s1.u);
        float z0 = fmaf((float)jj, s0.na, zs0);
        float z1 = fmaf((float)jj, s1.na, zs1);
        float e0 = ex2a(z0),            e1 = ex2a(z1);   // saturate safely
        float g0 = rcpa(1.0f + e0),     g1 = rcpa(1.0f + e1);
        float q0 = fmaf(s0.mu, s0.F, 1e-12f);
        float q1 = fmaf(s1.mu, s1.F, 1e-12f);
        s0.F = __saturatef(fmaf(g0, q0, s0.F));
        s1.F = __saturatef(fmaf(g1, q1, s1.F));
        sp0[jj] = fmaf(s0.kf, s0.F, fmaf(s0.nkd, s0.u, s0.kd));
        sp1[jj] = fmaf(s1.kf, s1.F, fmaf(s1.nkd, s1.u, s1.kd));
    }
}

template <int LEN>
__device__ __forceinline__ void do_group2(LS& s0, LS& s1, bool d_cheap,
                                          bool warp_geo, float* sp0, float* sp1,
                                          int n0g)
{
    float zs0 = fmaf((float)n0g, s0.na, s0.z0);
    float ze0 = fmaf((float)LEN, s0.na, zs0);
    float zs1 = fmaf((float)n0g, s1.na, s1.z0);
    float ze1 = fmaf((float)LEN, s1.na, zs1);
    // e pinned at reseed (inf/FTZ-0) while true g crosses back (z monotone)
    bool pc = ((zs0 >  126.0f && ze0 <  26.0f) ||
               (zs0 < -126.0f && ze0 > -26.0f) ||
               (zs1 >  126.0f && ze1 <  26.0f) ||
               (zs1 < -126.0f && ze1 > -26.0f));
    bool cheap = d_cheap && warp_geo && !__any_sync(0xffffffffu, pc);
    if (cheap) group_fast<LEN>(s0, s1, sp0, sp1, n0g);
    else       group_exact<LEN>(s0, s1, sp0, sp1, n0g);
}

__global__ void __launch_bounds__(BT, 7) ist2_kernel(
    const float* __restrict__ in, float* __restrict__ out)
{
    __shared__ float sm[ROWS * SW];    // 16.9 KB
    int t = threadIdx.x;
    int base_lane = blockIdx.x * ROWS;

    LS s0, s1;
    ls_init(s0, in + (size_t)(base_lane + t) * 7);
    ls_init(s1, in + (size_t)(base_lane + t + BT) * 7);

    // Warp-uniform gates over both lanes of every thread
    bool warp_geo = __all_sync(0xffffffffu,
        fabsf(s0.na) < 126.0f && fabsf(s1.na) < 126.0f);
    bool d_cheap  = __all_sync(0xffffffffu,
        (s0.beta * s0.lam < 0.05f) && (s1.beta * s1.lam < 0.05f));

    float* sp0 = &sm[t * SW];
    float* sp1 = &sm[(t + BT) * SW];

    #pragma unroll 1
    for (int chunk = 0; chunk < 7; ++chunk) {
        int n0 = chunk * 32;
        bool full = (chunk < 6);       // 200 = 6*32 + 8

        if (full) {
            do_group2<16>(s0, s1, d_cheap, warp_geo, sp0, sp1, n0);
            do_group2<16>(s0, s1, d_cheap, warp_geo, sp0 + 16, sp1 + 16, n0 + 16);
        } else {
            do_group2<8>(s0, s1, d_cheap, warp_geo, sp0, sp1, n0);
        }
        __syncthreads();
        // coalesced flush
        if (full) {
            // 128 rows x 32 cols = 1024 float4, 16 per thread
            #pragma unroll
            for (int it = 0; it < 16; ++it) {
                int q4 = it * BT + t;
                int r  = q4 >> 3;              // row 0..127
                int cc = (q4 & 7) * 4;         // col 0..28
                int sb = r * SW + cc;
                float4 v;
                v.x = sm[sb];
                v.y = sm[sb + 1];
                v.z = sm[sb + 2];
                v.w = sm[sb + 3];
                *reinterpret_cast<float4*>(
                    &out[(size_t)(base_lane + r) * 200 + n0 + cc]) = v;
            }
        } else {
            // 128 rows x 8 cols = 256 float4, 4 per thread
            #pragma unroll
            for (int it = 0; it < 4; ++it) {
                int q4 = it * BT + t;
                int r  = q4 >> 1;
                int cc = (q4 & 1) * 4;
                int sb = r * SW + cc;
                float4 v;
                v.x = sm[sb];
                v.y = sm[sb + 1];
                v.z = sm[sb + 2];
                v.w = sm[sb + 3];
                *reinterpret_cast<float4*>(
                    &out[(size_t)(base_lane + r) * 200 + n0 + cc]) = v;
            }
        }
        __syncthreads();
    }
}

// generic fallback for unexpected shapes
__global__ void __launch_bounds__(256) ist_generic(
    const float* __restrict__ in, float* __restrict__ out, int n_lanes)
{
    int tid = blockIdx.x * blockDim.x + threadIdx.x;
    if (tid >= n_lanes) return;
    const float* p = in + (size_t)tid * 7;
    float lam  = 0.001f * fmaxf(p[0], 0.0f);
    float beta = fmaf(10.0f, fmaxf(p[1], 0.0f), 1.0f);
    float kd = p[2], mu = p[3], kf = p[4];
    float a = LOG2E_F / p[6], z0 = p[5] * a;
    float u = 1.0f, F = 1e-12f, nf = 0.0f;
    float* o = out + (size_t)tid * 200;
    for (int n = 0; n < 200; ++n) {
        float l  = lg2a(fmaxf(u, 1e-12f));
        float pw = ex2a(beta * l);
        u = fminf(fmaxf(fmaf(-lam, pw, u), 0.0f), 1.0f);
        float z = fmaf(-nf, a, z0);
        float g = rcpa(1.0f + ex2a(z));
        float q = fmaf(mu, F, 1e-12f);
        F = __saturatef(fmaf(g, q, F));
        o[n] = fmaf(kf, F, fmaf(-kd, u, kd));
        nf += 1.0f;
    }
}

extern "C" void kernel_launch(void* const* d_in, const int* in_sizes, int n_in,
                              void* d_out, int out_size)
{
    const float* in = (const float*)d_in[0];
    float* out = (float*)d_out;
    int n_lanes = in_sizes[0] / 7;
    if (n_lanes % ROWS == 0) {
        ist2_kernel<<<n_lanes / ROWS, BT>>>(in, out);
    } else {
        ist_generic<<<(n_lanes + 255) / 256, 256>>>(in, out, n_lanes);
    }
}